// round 9
// baseline (speedup 1.0000x reference)
#include <cuda_runtime.h>
#include <cuda_bf16.h>
#include <cstdint>

// Problem dims (fixed by the reference)
#define T_   2048   // tokens (B*S)
#define H_   2048   // hidden
#define E_   16     // routed experts
#define K_   4      // top-k
#define I_   1408   // routed intermediate
#define IS_  2816   // shared intermediate
#define CAP_ 1024   // per-expert capacity

// ---------------- scratch (device globals; no allocations allowed) ----------
__device__ float g_Gr[E_ * CAP_ * I_];      // routed gate activations  [E,CAP,I]
__device__ float g_Mr[E_ * CAP_ * I_];      // routed mid = silu(g)*up  [E,CAP,I]
__device__ float g_Eout[E_ * CAP_ * H_];    // routed expert outputs    [E,CAP,H]
__device__ float g_Gs[T_ * IS_];            // shared gate activations  [T,IS]
__device__ float g_Ms[T_ * IS_];            // shared mid               [T,IS]
__device__ int   g_buf[E_ * CAP_];          // token id per (expert,slot)
__device__ int   g_pos[T_ * K_];            // slot of (token,k); -1 if dropped
__device__ int   g_cnt[E_];                 // filled slots per expert
__device__ int   g_ti[T_ * K_];             // top-k expert ids
__device__ float g_tw[T_ * K_];             // normalized top-k weights

// ======================= helpers ==============================
__device__ __forceinline__ uint32_t smem_u32(const void* p) {
    uint32_t a;
    asm("{ .reg .u64 t; cvta.to.shared.u64 t, %1; cvt.u32.u64 %0, t; }"
        : "=r"(a) : "l"(p));
    return a;
}
__device__ __forceinline__ void ldsm4(uint32_t* r, uint32_t addr) {
    asm volatile("ldmatrix.sync.aligned.m8n8.x4.shared.b16 {%0,%1,%2,%3}, [%4];"
                 : "=r"(r[0]), "=r"(r[1]), "=r"(r[2]), "=r"(r[3]) : "r"(addr));
}
__device__ __forceinline__ void ldsm4t(uint32_t* r, uint32_t addr) {
    asm volatile("ldmatrix.sync.aligned.m8n8.x4.trans.shared.b16 {%0,%1,%2,%3}, [%4];"
                 : "=r"(r[0]), "=r"(r[1]), "=r"(r[2]), "=r"(r[3]) : "r"(addr));
}
__device__ __forceinline__ void mma16816(float* d, const uint32_t* a, const uint32_t* b) {
    asm volatile("mma.sync.aligned.m16n8k16.row.col.f32.bf16.bf16.f32 "
                 "{%0,%1,%2,%3}, {%4,%5,%6,%7}, {%8,%9}, {%0,%1,%2,%3};"
                 : "+f"(d[0]), "+f"(d[1]), "+f"(d[2]), "+f"(d[3])
                 : "r"(a[0]), "r"(a[1]), "r"(a[2]), "r"(a[3]), "r"(b[0]), "r"(b[1]));
}
__device__ __forceinline__ uint32_t pack_hi(float x, float y) {
    return (uint32_t)__bfloat16_as_ushort(__float2bfloat16_rn(x))
         | ((uint32_t)__bfloat16_as_ushort(__float2bfloat16_rn(y)) << 16);
}
__device__ __forceinline__ uint32_t pack_lo(float x, float y) {
    float rx = x - __bfloat162float(__float2bfloat16_rn(x));
    float ry = y - __bfloat162float(__float2bfloat16_rn(y));
    return (uint32_t)__bfloat16_as_ushort(__float2bfloat16_rn(rx))
         | ((uint32_t)__bfloat16_as_ushort(__float2bfloat16_rn(ry)) << 16);
}

// ---------------- gate: logits -> softmax-topk -> normalized weights --------
__global__ void gate_topk_kernel(const float* __restrict__ x,
                                 const float* __restrict__ gw)
{
    int t = blockIdx.x;
    const float* xr = x + (size_t)t * H_;
    float acc[E_];
#pragma unroll
    for (int e = 0; e < E_; e++) acc[e] = 0.f;

    for (int h = threadIdx.x; h < H_; h += 256) {
        float xv = xr[h];
#pragma unroll
        for (int e = 0; e < E_; e++) acc[e] += xv * gw[e * H_ + h];
    }
#pragma unroll
    for (int e = 0; e < E_; e++) {
#pragma unroll
        for (int o = 16; o > 0; o >>= 1)
            acc[e] += __shfl_down_sync(0xffffffffu, acc[e], o);
    }
    __shared__ float sw[8][E_];
    int warp = threadIdx.x >> 5, lane = threadIdx.x & 31;
    if (lane == 0) {
#pragma unroll
        for (int e = 0; e < E_; e++) sw[warp][e] = acc[e];
    }
    __syncthreads();
    if (threadIdx.x == 0) {
        float lg[E_];
#pragma unroll
        for (int e = 0; e < E_; e++) {
            float s = 0.f;
            for (int w = 0; w < 8; w++) s += sw[w][e];
            lg[e] = s;
        }
        float m = lg[0];
#pragma unroll
        for (int e = 1; e < E_; e++) m = fmaxf(m, lg[e]);

        bool used[E_];
#pragma unroll
        for (int e = 0; e < E_; e++) used[e] = false;

        float wsel[K_]; int isel[K_]; float s = 0.f;
#pragma unroll
        for (int k = 0; k < K_; k++) {
            int best = 0; float bv = -1e30f;
            for (int e = 0; e < E_; e++)
                if (!used[e] && lg[e] > bv) { bv = lg[e]; best = e; }
            used[best] = true;
            isel[k] = best;
            wsel[k] = expf(lg[best] - m);
            s += wsel[k];
        }
        float inv = 1.f / s;
#pragma unroll
        for (int k = 0; k < K_; k++) {
            g_ti[t * K_ + k] = isel[k];
            g_tw[t * K_ + k] = wsel[k] * inv;
        }
    }
}

// ---------------- dispatch: stable rank within each expert -------------------
__global__ void dispatch_kernel()
{
    int e   = blockIdx.x;
    int tid = threadIdx.x;
    const int PER = (T_ * K_) / 256;
    int base = tid * PER;

    int c = 0;
    for (int j = 0; j < PER; j++)
        if (g_ti[base + j] == e) c++;

    __shared__ int ps[256];
    ps[tid] = c;
    __syncthreads();
    for (int off = 1; off < 256; off <<= 1) {
        int v = 0;
        if (tid >= off) v = ps[tid - off];
        __syncthreads();
        ps[tid] += v;
        __syncthreads();
    }
    int total = ps[255];
    int rank  = ps[tid] - c;

    for (int j = 0; j < PER; j++) {
        int idx = base + j;
        if (g_ti[idx] == e) {
            if (rank < CAP_) {
                g_buf[e * CAP_ + rank] = idx >> 2;
                g_pos[idx] = rank;
            } else {
                g_pos[idx] = -1;
            }
            rank++;
        }
    }
    if (tid == 0) g_cnt[e] = total < CAP_ ? total : CAP_;
}

// ============ bf16x3 mma.sync GEMM, tile 128x128, Kc=32, 8 warps =============
// Double-buffered smem stages + split warp phase order for tensor/LSU overlap.
// C[M,N] = A[M,K] * B[K,N]  (A fp32 row-major, B fp32 row-major [K,N])
// GATHER: A rows via g_buf.  EPI==1: C = silu(G) * acc.
#define A_STR 80
#define B_STR 272
#define O_AH  0
#define O_AL  (128 * A_STR)                     // 10240
#define O_BH  (2 * 128 * A_STR)                 // 20480
#define O_BL  (2 * 128 * A_STR + 32 * B_STR)    // 29184
#define STAGE_SZ (2 * 128 * A_STR + 2 * 32 * B_STR)  // 37888
#define SM_DYN (2 * STAGE_SZ)                   // 75776

template <bool GATHER, int EPI>
__global__ __launch_bounds__(256)
void mma_gemm(const float* __restrict__ A, const float* __restrict__ B,
              float* __restrict__ C, const float* __restrict__ G,
              const int* __restrict__ rows, const int* __restrict__ cnt,
              int Mfull, int N, int Kd,
              long long sA, long long sB, long long sC)
{
    extern __shared__ char dsm[];
    const int z = blockIdx.z;
    int Mz = Mfull;
    if (cnt) { int c = cnt[z]; Mz = c < Mfull ? c : Mfull; }
    const int yblk = blockIdx.y * 128;
    if (yblk >= Mz) return;
    const int xblk = blockIdx.x * 128;

    const float* Bb = B + (size_t)z * sB;
    float*       Cb = C + (size_t)z * sC;
    const float* Gb = (EPI == 1) ? (G + (size_t)z * sC) : nullptr;

    const uint32_t sm = smem_u32(dsm);
    const int tid = threadIdx.x;
    const int wid = tid >> 5;
    const int lid = tid & 31;

    // ---- per-thread global load plan (4 A-float4, 4 B-float4 per chunk) ----
    const float* aPtr[4]; bool aV[4]; uint32_t aOff[4];
    const float* bPtr[4]; uint32_t bOff[4];
#pragma unroll
    for (int i = 0; i < 4; i++) {
        int f = tid + 256 * i;                 // 0..1023
        int row = f >> 3, k4 = f & 7;          // A: row, k-quad
        aOff[i] = (uint32_t)row * A_STR + k4 * 8;
        int mg = yblk + row;
        aV[i] = mg < Mz;
        long long r;
        const float* base;
        if (GATHER) { r = aV[i] ? (long long)rows[z * CAP_ + mg] : 0; base = A; }
        else        { r = mg; base = A + (size_t)z * sA; }
        aPtr[i] = base + r * (long long)Kd + 4 * k4;

        int k = f >> 5, n4 = f & 31;           // B: k-row, n-quad
        bOff[i] = (uint32_t)k * B_STR + n4 * 8;
        bPtr[i] = Bb + (size_t)k * N + xblk + 4 * n4;
    }

    // ---- warp compute geometry ----
    const int wm = wid & 3;        // row group: wm*32..+31
    const int wn = wid >> 2;       // col group: wn*64..+63
    const int l15 = lid & 15, lh = lid >> 4;
    const uint32_t aLaneH = O_AH + (uint32_t)(wm * 32 + l15) * A_STR + lh * 16;
    const uint32_t aLaneL = O_AL + (uint32_t)(wm * 32 + l15) * A_STR + lh * 16;
    const uint32_t bLaneH = O_BH + (uint32_t)l15 * B_STR + (uint32_t)(wn * 64 + lh * 8) * 2;
    const uint32_t bLaneL = O_BL + (uint32_t)l15 * B_STR + (uint32_t)(wn * 64 + lh * 8) * 2;

    float acc[2][8][4];
#pragma unroll
    for (int mt = 0; mt < 2; mt++)
#pragma unroll
        for (int nt = 0; nt < 8; nt++)
#pragma unroll
            for (int q = 0; q < 4; q++) acc[mt][nt][q] = 0.f;

    const int nch = Kd / 32;
    float4 pa[4], pb[4];

    // ---- prologue: load chunk 0, convert+store into stage 0 ----
#pragma unroll
    for (int i = 0; i < 4; i++) {
        pa[i] = aV[i] ? *(const float4*)(aPtr[i]) : make_float4(0.f, 0.f, 0.f, 0.f);
        pb[i] = *(const float4*)(bPtr[i]);
    }
#pragma unroll
    for (int i = 0; i < 4; i++) {
        *(uint2*)(dsm + O_AH + aOff[i]) =
            make_uint2(pack_hi(pa[i].x, pa[i].y), pack_hi(pa[i].z, pa[i].w));
        *(uint2*)(dsm + O_AL + aOff[i]) =
            make_uint2(pack_lo(pa[i].x, pa[i].y), pack_lo(pa[i].z, pa[i].w));
        *(uint2*)(dsm + O_BH + bOff[i]) =
            make_uint2(pack_hi(pb[i].x, pb[i].y), pack_hi(pb[i].z, pb[i].w));
        *(uint2*)(dsm + O_BL + bOff[i]) =
            make_uint2(pack_lo(pb[i].x, pb[i].y), pack_lo(pb[i].z, pb[i].w));
    }
    __syncthreads();

    for (int ch = 0; ch < nch; ch++) {
        const uint32_t curB = (uint32_t)((ch & 1) * STAGE_SZ);
        char* const nxtP = dsm + ((ch + 1) & 1) * STAGE_SZ;
        const bool more = (ch + 1) < nch;

        // issue next chunk's global loads first (latency hides under MMA)
        if (more) {
            int ko = (ch + 1) * 32;
#pragma unroll
            for (int i = 0; i < 4; i++) {
                pa[i] = aV[i] ? *(const float4*)(aPtr[i] + ko)
                              : make_float4(0.f, 0.f, 0.f, 0.f);
                pb[i] = *(const float4*)(bPtr[i] + (size_t)ko * N);
            }
        }

        // phase bodies as lambdas
        auto storePhase = [&]() {
            if (!more) return;
#pragma unroll
            for (int i = 0; i < 4; i++) {
                *(uint2*)(nxtP + O_AH + aOff[i]) =
                    make_uint2(pack_hi(pa[i].x, pa[i].y), pack_hi(pa[i].z, pa[i].w));
                *(uint2*)(nxtP + O_AL + aOff[i]) =
                    make_uint2(pack_lo(pa[i].x, pa[i].y), pack_lo(pa[i].z, pa[i].w));
                *(uint2*)(nxtP + O_BH + bOff[i]) =
                    make_uint2(pack_hi(pb[i].x, pb[i].y), pack_hi(pb[i].z, pb[i].w));
                *(uint2*)(nxtP + O_BL + bOff[i]) =
                    make_uint2(pack_lo(pb[i].x, pb[i].y), pack_lo(pb[i].z, pb[i].w));
            }
        };
        auto mmaPhase = [&]() {
            const uint32_t aAdH = sm + curB + aLaneH;
            const uint32_t aAdL = sm + curB + aLaneL;
            const uint32_t bAdH = sm + curB + bLaneH;
            const uint32_t bAdL = sm + curB + bLaneL;
#pragma unroll
            for (int kk = 0; kk < 2; kk++) {
                uint32_t ah[2][4], al[2][4], bh[4][4], bl[4][4];
#pragma unroll
                for (int mt = 0; mt < 2; mt++) {
                    ldsm4(ah[mt], aAdH + mt * 16 * A_STR + kk * 32);
                    ldsm4(al[mt], aAdL + mt * 16 * A_STR + kk * 32);
                }
#pragma unroll
                for (int nt = 0; nt < 4; nt++) {
                    ldsm4t(bh[nt], bAdH + kk * 16 * B_STR + nt * 32);
                    ldsm4t(bl[nt], bAdL + kk * 16 * B_STR + nt * 32);
                }
#pragma unroll
                for (int mt = 0; mt < 2; mt++)
#pragma unroll
                    for (int nt = 0; nt < 4; nt++) {
                        mma16816(acc[mt][2 * nt],     ah[mt], &bh[nt][0]);
                        mma16816(acc[mt][2 * nt + 1], ah[mt], &bh[nt][2]);
                        mma16816(acc[mt][2 * nt],     ah[mt], &bl[nt][0]);
                        mma16816(acc[mt][2 * nt + 1], ah[mt], &bl[nt][2]);
                        mma16816(acc[mt][2 * nt],     al[mt], &bh[nt][0]);
                        mma16816(acc[mt][2 * nt + 1], al[mt], &bh[nt][2]);
                    }
            }
        };

        // split phase order: half the warps keep the tensor pipe busy while
        // the other half drive LSU/convert, then they swap.
        if (wid & 1) { storePhase(); mmaPhase(); }
        else         { mmaPhase();  storePhase(); }

        __syncthreads();
    }

    // ---- epilogue: write accumulators ----
    const int group = lid >> 2, tig = lid & 3;
#pragma unroll
    for (int mt = 0; mt < 2; mt++) {
        int r0 = yblk + wm * 32 + mt * 16 + group;
#pragma unroll
        for (int half = 0; half < 2; half++) {
            int r = r0 + half * 8;
            if (r < Mz) {
                size_t rowoff = (size_t)r * N;
#pragma unroll
                for (int nt = 0; nt < 8; nt++) {
                    int col = xblk + wn * 64 + nt * 8 + 2 * tig;
                    float d0 = acc[mt][nt][2 * half];
                    float d1 = acc[mt][nt][2 * half + 1];
                    if (EPI == 1) {
                        float2 g = *(const float2*)&Gb[rowoff + col];
                        d0 *= g.x / (1.f + __expf(-g.x));
                        d1 *= g.y / (1.f + __expf(-g.y));
                    }
                    *(float2*)&Cb[rowoff + col] = make_float2(d0, d1);
                }
            }
        }
    }
}

// ---------------- combine: out[t] += sum_k w * eout[e_k, pos_k] --------------
__global__ void combine_kernel(float* __restrict__ out)
{
    int t   = blockIdx.x;
    int tid = threadIdx.x;

    const float* rp[K_]; float w[K_]; bool v[K_];
#pragma unroll
    for (int k = 0; k < K_; k++) {
        int p = g_pos[t * K_ + k];
        int e = g_ti[t * K_ + k];
        w[k]  = g_tw[t * K_ + k];
        v[k]  = (p >= 0);
        int pc = p < 0 ? 0 : p;
        rp[k] = g_Eout + ((size_t)e * CAP_ + pc) * H_;
    }
#pragma unroll
    for (int j = 0; j < 2; j++) {
        int c4 = tid + j * 256;
        size_t off = (size_t)t * H_ + c4 * 4;
        float4 a = *(float4*)&out[off];
#pragma unroll
        for (int k = 0; k < K_; k++) {
            if (v[k]) {
                float4 xv = *(const float4*)&rp[k][c4 * 4];
                a.x += w[k] * xv.x; a.y += w[k] * xv.y;
                a.z += w[k] * xv.z; a.w += w[k] * xv.w;
            }
        }
        *(float4*)&out[off] = a;
    }
}

// ---------------- launch ------------------------------------------------------
extern "C" void kernel_launch(void* const* d_in, const int* in_sizes, int n_in,
                              void* d_out, int out_size)
{
    const float* x       = (const float*)d_in[0];
    const float* gate_w  = (const float*)d_in[1];
    const float* w_gate  = (const float*)d_in[2];
    const float* w_up    = (const float*)d_in[3];
    const float* w_down  = (const float*)d_in[4];
    const float* sw_gate = (const float*)d_in[5];
    const float* sw_up   = (const float*)d_in[6];
    const float* sw_down = (const float*)d_in[7];
    float* out = (float*)d_out;

    float *Gr, *Mr, *Eo, *Gs, *Ms;
    int *buf, *cnt;
    cudaGetSymbolAddress((void**)&Gr,  g_Gr);
    cudaGetSymbolAddress((void**)&Mr,  g_Mr);
    cudaGetSymbolAddress((void**)&Eo,  g_Eout);
    cudaGetSymbolAddress((void**)&Gs,  g_Gs);
    cudaGetSymbolAddress((void**)&Ms,  g_Ms);
    cudaGetSymbolAddress((void**)&buf, g_buf);
    cudaGetSymbolAddress((void**)&cnt, g_cnt);

    cudaFuncSetAttribute(mma_gemm<true, 0>,  cudaFuncAttributeMaxDynamicSharedMemorySize, SM_DYN);
    cudaFuncSetAttribute(mma_gemm<true, 1>,  cudaFuncAttributeMaxDynamicSharedMemorySize, SM_DYN);
    cudaFuncSetAttribute(mma_gemm<false, 0>, cudaFuncAttributeMaxDynamicSharedMemorySize, SM_DYN);
    cudaFuncSetAttribute(mma_gemm<false, 1>, cudaFuncAttributeMaxDynamicSharedMemorySize, SM_DYN);

    // 1) routing
    gate_topk_kernel<<<T_, 256>>>(x, gate_w);
    dispatch_kernel<<<E_, 256>>>();

    // 2) routed experts
    dim3 g1(I_ / 128, CAP_ / 128, E_);
    mma_gemm<true, 0><<<g1, 256, SM_DYN>>>(x, w_gate, Gr, nullptr, buf, cnt,
        CAP_, I_, H_, 0, (long long)H_ * I_, (long long)CAP_ * I_);
    mma_gemm<true, 1><<<g1, 256, SM_DYN>>>(x, w_up, Mr, Gr, buf, cnt,
        CAP_, I_, H_, 0, (long long)H_ * I_, (long long)CAP_ * I_);
    dim3 g2(H_ / 128, CAP_ / 128, E_);
    mma_gemm<false, 0><<<g2, 256, SM_DYN>>>(Mr, w_down, Eo, nullptr, nullptr, cnt,
        CAP_, H_, I_, (long long)CAP_ * I_, (long long)I_ * H_, (long long)CAP_ * H_);

    // 3) shared expert
    dim3 g3(IS_ / 128, T_ / 128, 1);
    mma_gemm<false, 0><<<g3, 256, SM_DYN>>>(x, sw_gate, Gs, nullptr, nullptr, nullptr,
        T_, IS_, H_, 0, 0, 0);
    mma_gemm<false, 1><<<g3, 256, SM_DYN>>>(x, sw_up, Ms, Gs, nullptr, nullptr,
        T_, IS_, H_, 0, 0, 0);
    dim3 g4(H_ / 128, T_ / 128, 1);
    mma_gemm<false, 0><<<g4, 256, SM_DYN>>>(Ms, sw_down, out, nullptr, nullptr, nullptr,
        T_, H_, IS_, 0, 0, 0);

    // 4) combine routed contributions (deterministic gather, no atomics)
    combine_kernel<<<T_, 256>>>(out);
}

// round 10
// speedup vs baseline: 1.3996x; 1.3996x over previous
#include <cuda_runtime.h>
#include <cuda_bf16.h>
#include <cstdint>

// Problem dims (fixed by the reference)
#define T_   2048   // tokens (B*S)
#define H_   2048   // hidden
#define E_   16     // routed experts
#define K_   4      // top-k
#define I_   1408   // routed intermediate
#define IS_  2816   // shared intermediate
#define CAP_ 1024   // per-expert capacity

// ---------------- scratch (device globals; no allocations allowed) ----------
__device__ float g_Gr[E_ * CAP_ * I_];      // routed gate activations  [E,CAP,I]
__device__ float g_Eout[E_ * CAP_ * H_];    // routed expert outputs    [E,CAP,H]
__device__ float g_Gs[T_ * IS_];            // shared gate activations  [T,IS]
__device__ int   g_buf[E_ * CAP_];          // token id per (expert,slot)
__device__ int   g_pos[T_ * K_];            // slot of (token,k); -1 if dropped
__device__ int   g_cnt[E_];                 // filled slots per expert
__device__ int   g_ti[T_ * K_];             // top-k expert ids
__device__ float g_tw[T_ * K_];             // normalized top-k weights

// bf16 hi/lo decompositions (preconverted per launch)
__device__ __align__(128) __nv_bfloat16 g_xH[T_ * H_],  g_xL[T_ * H_];
__device__ __align__(128) __nv_bfloat16 g_wgH[E_ * H_ * I_], g_wgL[E_ * H_ * I_];
__device__ __align__(128) __nv_bfloat16 g_wuH[E_ * H_ * I_], g_wuL[E_ * H_ * I_];
__device__ __align__(128) __nv_bfloat16 g_wdH[E_ * I_ * H_], g_wdL[E_ * I_ * H_];
__device__ __align__(128) __nv_bfloat16 g_sgH[H_ * IS_], g_sgL[H_ * IS_];
__device__ __align__(128) __nv_bfloat16 g_suH[H_ * IS_], g_suL[H_ * IS_];
__device__ __align__(128) __nv_bfloat16 g_sdH[IS_ * H_], g_sdL[IS_ * H_];
__device__ __align__(128) __nv_bfloat16 g_MrH[E_ * CAP_ * I_], g_MrL[E_ * CAP_ * I_];
__device__ __align__(128) __nv_bfloat16 g_MsH[T_ * IS_], g_MsL[T_ * IS_];

// ======================= helpers ==============================
__device__ __forceinline__ uint32_t smem_u32(const void* p) {
    uint32_t a;
    asm("{ .reg .u64 t; cvta.to.shared.u64 t, %1; cvt.u32.u64 %0, t; }"
        : "=r"(a) : "l"(p));
    return a;
}
__device__ __forceinline__ void ldsm4(uint32_t* r, uint32_t addr) {
    asm volatile("ldmatrix.sync.aligned.m8n8.x4.shared.b16 {%0,%1,%2,%3}, [%4];"
                 : "=r"(r[0]), "=r"(r[1]), "=r"(r[2]), "=r"(r[3]) : "r"(addr));
}
__device__ __forceinline__ void ldsm4t(uint32_t* r, uint32_t addr) {
    asm volatile("ldmatrix.sync.aligned.m8n8.x4.trans.shared.b16 {%0,%1,%2,%3}, [%4];"
                 : "=r"(r[0]), "=r"(r[1]), "=r"(r[2]), "=r"(r[3]) : "r"(addr));
}
__device__ __forceinline__ void mma16816(float* d, const uint32_t* a, const uint32_t* b) {
    asm volatile("mma.sync.aligned.m16n8k16.row.col.f32.bf16.bf16.f32 "
                 "{%0,%1,%2,%3}, {%4,%5,%6,%7}, {%8,%9}, {%0,%1,%2,%3};"
                 : "+f"(d[0]), "+f"(d[1]), "+f"(d[2]), "+f"(d[3])
                 : "r"(a[0]), "r"(a[1]), "r"(a[2]), "r"(a[3]), "r"(b[0]), "r"(b[1]));
}
__device__ __forceinline__ uint32_t pack_hi(float x, float y) {
    return (uint32_t)__bfloat16_as_ushort(__float2bfloat16_rn(x))
         | ((uint32_t)__bfloat16_as_ushort(__float2bfloat16_rn(y)) << 16);
}
__device__ __forceinline__ uint32_t pack_lo(float x, float y) {
    float rx = x - __bfloat162float(__float2bfloat16_rn(x));
    float ry = y - __bfloat162float(__float2bfloat16_rn(y));
    return (uint32_t)__bfloat16_as_ushort(__float2bfloat16_rn(rx))
         | ((uint32_t)__bfloat16_as_ushort(__float2bfloat16_rn(ry)) << 16);
}
__device__ __forceinline__ void cpa16(uint32_t dst, const void* src) {
    asm volatile("cp.async.cg.shared.global [%0], [%1], 16;"
                 :: "r"(dst), "l"(src) : "memory");
}
#define CP_COMMIT() asm volatile("cp.async.commit_group;" ::: "memory")
#define CP_WAIT1()  asm volatile("cp.async.wait_group 1;" ::: "memory")

// ---------------- fp32 -> bf16 hi/lo pair conversion -------------------------
__global__ void cvt_pair_kernel(const float* __restrict__ src,
                                __nv_bfloat16* __restrict__ hi,
                                __nv_bfloat16* __restrict__ lo, int n4)
{
    int i = blockIdx.x * blockDim.x + threadIdx.x;
    if (i < n4) {
        float4 v = ((const float4*)src)[i];
        ((uint2*)hi)[i] = make_uint2(pack_hi(v.x, v.y), pack_hi(v.z, v.w));
        ((uint2*)lo)[i] = make_uint2(pack_lo(v.x, v.y), pack_lo(v.z, v.w));
    }
}

// ---------------- gate: logits -> softmax-topk -> normalized weights --------
__global__ void gate_topk_kernel(const float* __restrict__ x,
                                 const float* __restrict__ gw)
{
    int t = blockIdx.x;
    const float* xr = x + (size_t)t * H_;
    float acc[E_];
#pragma unroll
    for (int e = 0; e < E_; e++) acc[e] = 0.f;

    for (int h = threadIdx.x; h < H_; h += 256) {
        float xv = xr[h];
#pragma unroll
        for (int e = 0; e < E_; e++) acc[e] += xv * gw[e * H_ + h];
    }
#pragma unroll
    for (int e = 0; e < E_; e++) {
#pragma unroll
        for (int o = 16; o > 0; o >>= 1)
            acc[e] += __shfl_down_sync(0xffffffffu, acc[e], o);
    }
    __shared__ float sw[8][E_];
    int warp = threadIdx.x >> 5, lane = threadIdx.x & 31;
    if (lane == 0) {
#pragma unroll
        for (int e = 0; e < E_; e++) sw[warp][e] = acc[e];
    }
    __syncthreads();
    if (threadIdx.x == 0) {
        float lg[E_];
#pragma unroll
        for (int e = 0; e < E_; e++) {
            float s = 0.f;
            for (int w = 0; w < 8; w++) s += sw[w][e];
            lg[e] = s;
        }
        float m = lg[0];
#pragma unroll
        for (int e = 1; e < E_; e++) m = fmaxf(m, lg[e]);

        bool used[E_];
#pragma unroll
        for (int e = 0; e < E_; e++) used[e] = false;

        float wsel[K_]; int isel[K_]; float s = 0.f;
#pragma unroll
        for (int k = 0; k < K_; k++) {
            int best = 0; float bv = -1e30f;
            for (int e = 0; e < E_; e++)
                if (!used[e] && lg[e] > bv) { bv = lg[e]; best = e; }
            used[best] = true;
            isel[k] = best;
            wsel[k] = expf(lg[best] - m);
            s += wsel[k];
        }
        float inv = 1.f / s;
#pragma unroll
        for (int k = 0; k < K_; k++) {
            g_ti[t * K_ + k] = isel[k];
            g_tw[t * K_ + k] = wsel[k] * inv;
        }
    }
}

// ---------------- dispatch: stable rank within each expert -------------------
__global__ void dispatch_kernel()
{
    int e   = blockIdx.x;
    int tid = threadIdx.x;
    const int PER = (T_ * K_) / 256;
    int base = tid * PER;

    int c = 0;
    for (int j = 0; j < PER; j++)
        if (g_ti[base + j] == e) c++;

    __shared__ int ps[256];
    ps[tid] = c;
    __syncthreads();
    for (int off = 1; off < 256; off <<= 1) {
        int v = 0;
        if (tid >= off) v = ps[tid - off];
        __syncthreads();
        ps[tid] += v;
        __syncthreads();
    }
    int total = ps[255];
    int rank  = ps[tid] - c;

    for (int j = 0; j < PER; j++) {
        int idx = base + j;
        if (g_ti[idx] == e) {
            if (rank < CAP_) {
                g_buf[e * CAP_ + rank] = idx >> 2;
                g_pos[idx] = rank;
            } else {
                g_pos[idx] = -1;
            }
            rank++;
        }
    }
    if (tid == 0) g_cnt[e] = total < CAP_ ? total : CAP_;
}

// ===== bf16x3 mma.sync GEMM on preconverted hi/lo pairs, cp.async 3-stage ====
// C = A * B with A=[M,K] bf16 hi/lo row-major, B=[K,N] bf16 hi/lo row-major.
// GATHER: A rows via g_buf.  EPI 0: write fp32 C.  EPI 1: v=silu(G)*acc,
// write bf16 hi/lo pair (CH, CL).
#define A_STR 80
#define B_STR 272
#define O_AH  0
#define O_AL  (128 * A_STR)                      // 10240
#define O_BH  (2 * 128 * A_STR)                  // 20480
#define O_BL  (2 * 128 * A_STR + 32 * B_STR)     // 29184
#define STAGE_SZ (2 * 128 * A_STR + 2 * 32 * B_STR)   // 37888
#define NSTAGE 3
#define SM_DYN (NSTAGE * STAGE_SZ)               // 113664

template <bool GATHER, int EPI>
__global__ __launch_bounds__(256)
void mma_gemm(const __nv_bfloat16* __restrict__ AH, const __nv_bfloat16* __restrict__ AL,
              const __nv_bfloat16* __restrict__ BH, const __nv_bfloat16* __restrict__ BL,
              float* __restrict__ Cf,
              __nv_bfloat16* __restrict__ CH, __nv_bfloat16* __restrict__ CL,
              const float* __restrict__ G,
              const int* __restrict__ rows, const int* __restrict__ cnt,
              int Mfull, int N, int Kd,
              long long sA, long long sB, long long sC)
{
    extern __shared__ char dsm[];
    const int z = blockIdx.z;
    int Mz = Mfull;
    if (cnt) { int c = cnt[z]; Mz = c < Mfull ? c : Mfull; }
    const int yblk = blockIdx.y * 128;
    if (yblk >= Mz) return;
    const int xblk = blockIdx.x * 128;

    const uint32_t sm = smem_u32(dsm);
    const int tid = threadIdx.x;
    const int wid = tid >> 5;
    const int lid = tid & 31;

    // ---- cp.async plan: 8 x 16B granules per thread per chunk ----
    // A: granule g in 0..511: row=g>>2 (0..127), q=g&3 (16B within 64B row-chunk)
    // B: granule g in 0..511: k=g>>4 (0..31),  q=g&15 (16B within 256B n-row)
    const char* aSrcH[2]; const char* aSrcL[2]; uint32_t aDst[2];
    const char* bSrcH[2]; const char* bSrcL[2]; uint32_t bDst[2];
#pragma unroll
    for (int i = 0; i < 2; i++) {
        int g = tid + 256 * i;
        int row = g >> 2, q = g & 3;
        int mg = yblk + row;
        long long r;
        if (GATHER) r = (mg < Mz) ? (long long)rows[z * CAP_ + mg] : 0;
        else        r = (long long)z * 0 + mg;   // per-z base folded below
        const __nv_bfloat16* baseH = GATHER ? AH : (AH + (size_t)z * sA);
        const __nv_bfloat16* baseL = GATHER ? AL : (AL + (size_t)z * sA);
        aSrcH[i] = (const char*)(baseH + r * (long long)Kd) + q * 16;
        aSrcL[i] = (const char*)(baseL + r * (long long)Kd) + q * 16;
        aDst[i]  = (uint32_t)row * A_STR + q * 16;

        int k = g >> 4, q2 = g & 15;
        bSrcH[i] = (const char*)(BH + (size_t)z * sB + (size_t)k * N + xblk) + q2 * 16;
        bSrcL[i] = (const char*)(BL + (size_t)z * sB + (size_t)k * N + xblk) + q2 * 16;
        bDst[i]  = (uint32_t)k * B_STR + q2 * 16;
    }

    const int nch = Kd / 32;
    auto issueStage = [&](int ch) {
        if (ch >= nch) return;
        const uint32_t base = sm + (uint32_t)(ch % NSTAGE) * STAGE_SZ;
        const size_t aoff = (size_t)ch * 64;            // 32 bf16 = 64 bytes
        const size_t boff = (size_t)ch * 32 * N * 2;    // 32 k-rows
#pragma unroll
        for (int i = 0; i < 2; i++) {
            cpa16(base + O_AH + aDst[i], aSrcH[i] + aoff);
            cpa16(base + O_AL + aDst[i], aSrcL[i] + aoff);
            cpa16(base + O_BH + bDst[i], bSrcH[i] + boff);
            cpa16(base + O_BL + bDst[i], bSrcL[i] + boff);
        }
    };

    // ---- warp compute geometry ----
    const int wm = wid & 3;
    const int wn = wid >> 2;
    const int l15 = lid & 15, lh = lid >> 4;
    const uint32_t aLaneH = O_AH + (uint32_t)(wm * 32 + l15) * A_STR + lh * 16;
    const uint32_t aLaneL = O_AL + (uint32_t)(wm * 32 + l15) * A_STR + lh * 16;
    const uint32_t bLaneH = O_BH + (uint32_t)l15 * B_STR + (uint32_t)(wn * 64 + lh * 8) * 2;
    const uint32_t bLaneL = O_BL + (uint32_t)l15 * B_STR + (uint32_t)(wn * 64 + lh * 8) * 2;

    float acc[2][8][4];
#pragma unroll
    for (int mt = 0; mt < 2; mt++)
#pragma unroll
        for (int nt = 0; nt < 8; nt++)
#pragma unroll
            for (int q = 0; q < 4; q++) acc[mt][nt][q] = 0.f;

    // ---- prologue: stages 0 and 1 in flight ----
    issueStage(0); CP_COMMIT();
    issueStage(1); CP_COMMIT();

    for (int ch = 0; ch < nch; ch++) {
        CP_WAIT1();
        __syncthreads();

        issueStage(ch + 2);
        CP_COMMIT();

        const uint32_t sbase = sm + (uint32_t)(ch % NSTAGE) * STAGE_SZ;
        const uint32_t aAdH = sbase + aLaneH - sm + sm;   // keep simple adds
        const uint32_t curB = (uint32_t)(ch % NSTAGE) * STAGE_SZ;
        const uint32_t aH = sm + curB + aLaneH;
        const uint32_t aL = sm + curB + aLaneL;
        const uint32_t bH = sm + curB + bLaneH;
        const uint32_t bL = sm + curB + bLaneL;
        (void)sbase; (void)aAdH;
#pragma unroll
        for (int kk = 0; kk < 2; kk++) {
            uint32_t ah[2][4], al[2][4], bh[4][4], bl[4][4];
#pragma unroll
            for (int mt = 0; mt < 2; mt++) {
                ldsm4(ah[mt], aH + mt * 16 * A_STR + kk * 32);
                ldsm4(al[mt], aL + mt * 16 * A_STR + kk * 32);
            }
#pragma unroll
            for (int nt = 0; nt < 4; nt++) {
                ldsm4t(bh[nt], bH + kk * 16 * B_STR + nt * 32);
                ldsm4t(bl[nt], bL + kk * 16 * B_STR + nt * 32);
            }
#pragma unroll
            for (int mt = 0; mt < 2; mt++)
#pragma unroll
                for (int nt = 0; nt < 4; nt++) {
                    mma16816(acc[mt][2 * nt],     ah[mt], &bh[nt][0]);
                    mma16816(acc[mt][2 * nt + 1], ah[mt], &bh[nt][2]);
                    mma16816(acc[mt][2 * nt],     ah[mt], &bl[nt][0]);
                    mma16816(acc[mt][2 * nt + 1], ah[mt], &bl[nt][2]);
                    mma16816(acc[mt][2 * nt],     al[mt], &bh[nt][0]);
                    mma16816(acc[mt][2 * nt + 1], al[mt], &bh[nt][2]);
                }
        }
        __syncthreads();
    }

    // ---- epilogue ----
    const int group = lid >> 2, tig = lid & 3;
#pragma unroll
    for (int mt = 0; mt < 2; mt++) {
        int r0 = yblk + wm * 32 + mt * 16 + group;
#pragma unroll
        for (int half = 0; half < 2; half++) {
            int r = r0 + half * 8;
            if (r < Mz) {
                size_t rowoff = (size_t)r * N + (size_t)z * sC - (size_t)z * sC;
                rowoff = (size_t)r * N;
#pragma unroll
                for (int nt = 0; nt < 8; nt++) {
                    int col = xblk + wn * 64 + nt * 8 + 2 * tig;
                    float d0 = acc[mt][nt][2 * half];
                    float d1 = acc[mt][nt][2 * half + 1];
                    size_t off = (size_t)z * sC + rowoff + col;
                    if (EPI == 0) {
                        *(float2*)&Cf[off] = make_float2(d0, d1);
                    } else {
                        float2 g = *(const float2*)&G[off];
                        d0 *= g.x / (1.f + __expf(-g.x));
                        d1 *= g.y / (1.f + __expf(-g.y));
                        *(uint32_t*)&CH[off] = pack_hi(d0, d1);
                        *(uint32_t*)&CL[off] = pack_lo(d0, d1);
                    }
                }
            }
        }
    }
}

// ---------------- combine: out[t] += sum_k w * eout[e_k, pos_k] --------------
__global__ void combine_kernel(float* __restrict__ out)
{
    int t   = blockIdx.x;
    int tid = threadIdx.x;

    const float* rp[K_]; float w[K_]; bool v[K_];
#pragma unroll
    for (int k = 0; k < K_; k++) {
        int p = g_pos[t * K_ + k];
        int e = g_ti[t * K_ + k];
        w[k]  = g_tw[t * K_ + k];
        v[k]  = (p >= 0);
        int pc = p < 0 ? 0 : p;
        rp[k] = g_Eout + ((size_t)e * CAP_ + pc) * H_;
    }
#pragma unroll
    for (int j = 0; j < 2; j++) {
        int c4 = tid + j * 256;
        size_t off = (size_t)t * H_ + c4 * 4;
        float4 a = *(float4*)&out[off];
#pragma unroll
        for (int k = 0; k < K_; k++) {
            if (v[k]) {
                float4 xv = *(const float4*)&rp[k][c4 * 4];
                a.x += w[k] * xv.x; a.y += w[k] * xv.y;
                a.z += w[k] * xv.z; a.w += w[k] * xv.w;
            }
        }
        *(float4*)&out[off] = a;
    }
}

// ---------------- launch ------------------------------------------------------
extern "C" void kernel_launch(void* const* d_in, const int* in_sizes, int n_in,
                              void* d_out, int out_size)
{
    const float* x       = (const float*)d_in[0];
    const float* gate_w  = (const float*)d_in[1];
    const float* w_gate  = (const float*)d_in[2];
    const float* w_up    = (const float*)d_in[3];
    const float* w_down  = (const float*)d_in[4];
    const float* sw_gate = (const float*)d_in[5];
    const float* sw_up   = (const float*)d_in[6];
    const float* sw_down = (const float*)d_in[7];
    float* out = (float*)d_out;

    float *Gr, *Eo, *Gs;
    int *buf, *cnt;
    __nv_bfloat16 *xH, *xL, *wgH, *wgL, *wuH, *wuL, *wdH, *wdL;
    __nv_bfloat16 *sgH, *sgL, *suH, *suL, *sdH, *sdL, *MrH, *MrL, *MsH, *MsL;
    cudaGetSymbolAddress((void**)&Gr,  g_Gr);
    cudaGetSymbolAddress((void**)&Eo,  g_Eout);
    cudaGetSymbolAddress((void**)&Gs,  g_Gs);
    cudaGetSymbolAddress((void**)&buf, g_buf);
    cudaGetSymbolAddress((void**)&cnt, g_cnt);
    cudaGetSymbolAddress((void**)&xH,  g_xH);  cudaGetSymbolAddress((void**)&xL,  g_xL);
    cudaGetSymbolAddress((void**)&wgH, g_wgH); cudaGetSymbolAddress((void**)&wgL, g_wgL);
    cudaGetSymbolAddress((void**)&wuH, g_wuH); cudaGetSymbolAddress((void**)&wuL, g_wuL);
    cudaGetSymbolAddress((void**)&wdH, g_wdH); cudaGetSymbolAddress((void**)&wdL, g_wdL);
    cudaGetSymbolAddress((void**)&sgH, g_sgH); cudaGetSymbolAddress((void**)&sgL, g_sgL);
    cudaGetSymbolAddress((void**)&suH, g_suH); cudaGetSymbolAddress((void**)&suL, g_suL);
    cudaGetSymbolAddress((void**)&sdH, g_sdH); cudaGetSymbolAddress((void**)&sdL, g_sdL);
    cudaGetSymbolAddress((void**)&MrH, g_MrH); cudaGetSymbolAddress((void**)&MrL, g_MrL);
    cudaGetSymbolAddress((void**)&MsH, g_MsH); cudaGetSymbolAddress((void**)&MsL, g_MsL);

    cudaFuncSetAttribute(mma_gemm<true, 0>,  cudaFuncAttributeMaxDynamicSharedMemorySize, SM_DYN);
    cudaFuncSetAttribute(mma_gemm<true, 1>,  cudaFuncAttributeMaxDynamicSharedMemorySize, SM_DYN);
    cudaFuncSetAttribute(mma_gemm<false, 0>, cudaFuncAttributeMaxDynamicSharedMemorySize, SM_DYN);
    cudaFuncSetAttribute(mma_gemm<false, 1>, cudaFuncAttributeMaxDynamicSharedMemorySize, SM_DYN);

    // 0) preconvert fp32 -> bf16 hi/lo pairs
    auto cvt = [&](const float* s, __nv_bfloat16* h, __nv_bfloat16* l, long long n) {
        int n4 = (int)(n / 4);
        cvt_pair_kernel<<<(n4 + 255) / 256, 256>>>(s, h, l, n4);
    };
    cvt(x,       xH,  xL,  (long long)T_ * H_);
    cvt(w_gate,  wgH, wgL, (long long)E_ * H_ * I_);
    cvt(w_up,    wuH, wuL, (long long)E_ * H_ * I_);
    cvt(w_down,  wdH, wdL, (long long)E_ * I_ * H_);
    cvt(sw_gate, sgH, sgL, (long long)H_ * IS_);
    cvt(sw_up,   suH, suL, (long long)H_ * IS_);
    cvt(sw_down, sdH, sdL, (long long)IS_ * H_);

    // 1) routing
    gate_topk_kernel<<<T_, 256>>>(x, gate_w);
    dispatch_kernel<<<E_, 256>>>();

    // 2) routed experts
    dim3 g1(I_ / 128, CAP_ / 128, E_);
    mma_gemm<true, 0><<<g1, 256, SM_DYN>>>(xH, xL, wgH, wgL, Gr, nullptr, nullptr, nullptr,
        buf, cnt, CAP_, I_, H_, 0, (long long)H_ * I_, (long long)CAP_ * I_);
    mma_gemm<true, 1><<<g1, 256, SM_DYN>>>(xH, xL, wuH, wuL, nullptr, MrH, MrL, Gr,
        buf, cnt, CAP_, I_, H_, 0, (long long)H_ * I_, (long long)CAP_ * I_);
    dim3 g2(H_ / 128, CAP_ / 128, E_);
    mma_gemm<false, 0><<<g2, 256, SM_DYN>>>(MrH, MrL, wdH, wdL, Eo, nullptr, nullptr, nullptr,
        nullptr, cnt, CAP_, H_, I_, (long long)CAP_ * I_, (long long)I_ * H_, (long long)CAP_ * H_);

    // 3) shared expert
    dim3 g3(IS_ / 128, T_ / 128, 1);
    mma_gemm<false, 0><<<g3, 256, SM_DYN>>>(xH, xL, sgH, sgL, Gs, nullptr, nullptr, nullptr,
        nullptr, nullptr, T_, IS_, H_, 0, 0, 0);
    mma_gemm<false, 1><<<g3, 256, SM_DYN>>>(xH, xL, suH, suL, nullptr, MsH, MsL, Gs,
        nullptr, nullptr, T_, IS_, H_, 0, 0, 0);
    dim3 g4(H_ / 128, T_ / 128, 1);
    mma_gemm<false, 0><<<g4, 256, SM_DYN>>>(MsH, MsL, sdH, sdL, out, nullptr, nullptr, nullptr,
        nullptr, nullptr, T_, H_, IS_, 0, 0, 0);

    // 4) combine routed contributions (deterministic gather, no atomics)
    combine_kernel<<<T_, 256>>>(out);
}

// round 11
// speedup vs baseline: 1.4484x; 1.0349x over previous
#include <cuda_runtime.h>
#include <cuda_bf16.h>
#include <cstdint>

// Problem dims (fixed by the reference)
#define T_   2048   // tokens (B*S)
#define H_   2048   // hidden
#define E_   16     // routed experts
#define K_   4      // top-k
#define I_   1408   // routed intermediate
#define IS_  2816   // shared intermediate
#define CAP_ 1024   // per-expert capacity

// ---------------- scratch (device globals; no allocations allowed) ----------
__device__ float g_Gr[E_ * CAP_ * I_];      // routed gate activations  [E,CAP,I]
__device__ float g_Eout[E_ * CAP_ * H_];    // routed expert outputs    [E,CAP,H]
__device__ float g_Gs[T_ * IS_];            // shared gate activations  [T,IS]
__device__ int   g_buf[E_ * CAP_];          // token id per (expert,slot)
__device__ int   g_pos[T_ * K_];            // slot of (token,k); -1 if dropped
__device__ int   g_cnt[E_];                 // filled slots per expert
__device__ int   g_ti[T_ * K_];             // top-k expert ids
__device__ float g_tw[T_ * K_];             // normalized top-k weights

// bf16 hi/lo decompositions (preconverted per launch)
__device__ __align__(128) __nv_bfloat16 g_xH[T_ * H_],  g_xL[T_ * H_];
__device__ __align__(128) __nv_bfloat16 g_wgH[E_ * H_ * I_], g_wgL[E_ * H_ * I_];
__device__ __align__(128) __nv_bfloat16 g_wuH[E_ * H_ * I_], g_wuL[E_ * H_ * I_];
__device__ __align__(128) __nv_bfloat16 g_wdH[E_ * I_ * H_], g_wdL[E_ * I_ * H_];
__device__ __align__(128) __nv_bfloat16 g_sgH[H_ * IS_], g_sgL[H_ * IS_];
__device__ __align__(128) __nv_bfloat16 g_suH[H_ * IS_], g_suL[H_ * IS_];
__device__ __align__(128) __nv_bfloat16 g_sdH[IS_ * H_], g_sdL[IS_ * H_];
__device__ __align__(128) __nv_bfloat16 g_MrH[E_ * CAP_ * I_], g_MrL[E_ * CAP_ * I_];
__device__ __align__(128) __nv_bfloat16 g_MsH[T_ * IS_], g_MsL[T_ * IS_];

// ======================= helpers ==============================
__device__ __forceinline__ uint32_t smem_u32(const void* p) {
    uint32_t a;
    asm("{ .reg .u64 t; cvta.to.shared.u64 t, %1; cvt.u32.u64 %0, t; }"
        : "=r"(a) : "l"(p));
    return a;
}
__device__ __forceinline__ void ldsm4(uint32_t* r, uint32_t addr) {
    asm volatile("ldmatrix.sync.aligned.m8n8.x4.shared.b16 {%0,%1,%2,%3}, [%4];"
                 : "=r"(r[0]), "=r"(r[1]), "=r"(r[2]), "=r"(r[3]) : "r"(addr));
}
__device__ __forceinline__ void ldsm4t(uint32_t* r, uint32_t addr) {
    asm volatile("ldmatrix.sync.aligned.m8n8.x4.trans.shared.b16 {%0,%1,%2,%3}, [%4];"
                 : "=r"(r[0]), "=r"(r[1]), "=r"(r[2]), "=r"(r[3]) : "r"(addr));
}
__device__ __forceinline__ void mma16816(float* d, const uint32_t* a, const uint32_t* b) {
    asm volatile("mma.sync.aligned.m16n8k16.row.col.f32.bf16.bf16.f32 "
                 "{%0,%1,%2,%3}, {%4,%5,%6,%7}, {%8,%9}, {%0,%1,%2,%3};"
                 : "+f"(d[0]), "+f"(d[1]), "+f"(d[2]), "+f"(d[3])
                 : "r"(a[0]), "r"(a[1]), "r"(a[2]), "r"(a[3]), "r"(b[0]), "r"(b[1]));
}
__device__ __forceinline__ uint32_t pack_hi(float x, float y) {
    return (uint32_t)__bfloat16_as_ushort(__float2bfloat16_rn(x))
         | ((uint32_t)__bfloat16_as_ushort(__float2bfloat16_rn(y)) << 16);
}
__device__ __forceinline__ uint32_t pack_lo(float x, float y) {
    float rx = x - __bfloat162float(__float2bfloat16_rn(x));
    float ry = y - __bfloat162float(__float2bfloat16_rn(y));
    return (uint32_t)__bfloat16_as_ushort(__float2bfloat16_rn(rx))
         | ((uint32_t)__bfloat16_as_ushort(__float2bfloat16_rn(ry)) << 16);
}
__device__ __forceinline__ void cpa16(uint32_t dst, const void* src) {
    asm volatile("cp.async.cg.shared.global [%0], [%1], 16;"
                 :: "r"(dst), "l"(src) : "memory");
}
#define CP_COMMIT() asm volatile("cp.async.commit_group;" ::: "memory")
#define CP_WAIT1()  asm volatile("cp.async.wait_group 1;" ::: "memory")

// ---------------- fp32 -> bf16 hi/lo pair conversion -------------------------
__global__ void cvt_pair_kernel(const float* __restrict__ src,
                                __nv_bfloat16* __restrict__ hi,
                                __nv_bfloat16* __restrict__ lo, int n4)
{
    int i = blockIdx.x * blockDim.x + threadIdx.x;
    if (i < n4) {
        float4 v = ((const float4*)src)[i];
        ((uint2*)hi)[i] = make_uint2(pack_hi(v.x, v.y), pack_hi(v.z, v.w));
        ((uint2*)lo)[i] = make_uint2(pack_lo(v.x, v.y), pack_lo(v.z, v.w));
    }
}

// ---------------- gate: logits -> softmax-topk -> normalized weights --------
__global__ void gate_topk_kernel(const float* __restrict__ x,
                                 const float* __restrict__ gw)
{
    int t = blockIdx.x;
    const float* xr = x + (size_t)t * H_;
    float acc[E_];
#pragma unroll
    for (int e = 0; e < E_; e++) acc[e] = 0.f;

    for (int h = threadIdx.x; h < H_; h += 256) {
        float xv = xr[h];
#pragma unroll
        for (int e = 0; e < E_; e++) acc[e] += xv * gw[e * H_ + h];
    }
#pragma unroll
    for (int e = 0; e < E_; e++) {
#pragma unroll
        for (int o = 16; o > 0; o >>= 1)
            acc[e] += __shfl_down_sync(0xffffffffu, acc[e], o);
    }
    __shared__ float sw[8][E_];
    int warp = threadIdx.x >> 5, lane = threadIdx.x & 31;
    if (lane == 0) {
#pragma unroll
        for (int e = 0; e < E_; e++) sw[warp][e] = acc[e];
    }
    __syncthreads();
    if (threadIdx.x == 0) {
        float lg[E_];
#pragma unroll
        for (int e = 0; e < E_; e++) {
            float s = 0.f;
            for (int w = 0; w < 8; w++) s += sw[w][e];
            lg[e] = s;
        }
        float m = lg[0];
#pragma unroll
        for (int e = 1; e < E_; e++) m = fmaxf(m, lg[e]);

        bool used[E_];
#pragma unroll
        for (int e = 0; e < E_; e++) used[e] = false;

        float wsel[K_]; int isel[K_]; float s = 0.f;
#pragma unroll
        for (int k = 0; k < K_; k++) {
            int best = 0; float bv = -1e30f;
            for (int e = 0; e < E_; e++)
                if (!used[e] && lg[e] > bv) { bv = lg[e]; best = e; }
            used[best] = true;
            isel[k] = best;
            wsel[k] = expf(lg[best] - m);
            s += wsel[k];
        }
        float inv = 1.f / s;
#pragma unroll
        for (int k = 0; k < K_; k++) {
            g_ti[t * K_ + k] = isel[k];
            g_tw[t * K_ + k] = wsel[k] * inv;
        }
    }
}

// ---------------- dispatch: stable rank within each expert -------------------
__global__ void dispatch_kernel()
{
    int e   = blockIdx.x;
    int tid = threadIdx.x;
    const int PER = (T_ * K_) / 256;
    int base = tid * PER;

    int c = 0;
    for (int j = 0; j < PER; j++)
        if (g_ti[base + j] == e) c++;

    __shared__ int ps[256];
    ps[tid] = c;
    __syncthreads();
    for (int off = 1; off < 256; off <<= 1) {
        int v = 0;
        if (tid >= off) v = ps[tid - off];
        __syncthreads();
        ps[tid] += v;
        __syncthreads();
    }
    int total = ps[255];
    int rank  = ps[tid] - c;

    for (int j = 0; j < PER; j++) {
        int idx = base + j;
        if (g_ti[idx] == e) {
            if (rank < CAP_) {
                g_buf[e * CAP_ + rank] = idx >> 2;
                g_pos[idx] = rank;
            } else {
                g_pos[idx] = -1;
            }
            rank++;
        }
    }
    if (tid == 0) g_cnt[e] = total < CAP_ ? total : CAP_;
}

// == bf16x3 mma.sync GEMM, 512 threads, 16 warps, warp tile 32x32, 3 stages ==
// C = A * B with A=[M,K] bf16 hi/lo row-major, B=[K,N] bf16 hi/lo row-major.
// GATHER: A rows via g_buf.  EPI 0: write fp32 C.  EPI 1: v=silu(G)*acc,
// write bf16 hi/lo pair (CH, CL).
#define A_STR 80
#define B_STR 272
#define O_AH  0
#define O_AL  (128 * A_STR)                      // 10240
#define O_BH  (2 * 128 * A_STR)                  // 20480
#define O_BL  (2 * 128 * A_STR + 32 * B_STR)     // 29184
#define STAGE_SZ (2 * 128 * A_STR + 2 * 32 * B_STR)   // 37888
#define NSTAGE 3
#define SM_DYN (NSTAGE * STAGE_SZ)               // 113664

template <bool GATHER, int EPI>
__global__ __launch_bounds__(512)
void mma_gemm(const __nv_bfloat16* __restrict__ AH, const __nv_bfloat16* __restrict__ AL,
              const __nv_bfloat16* __restrict__ BH, const __nv_bfloat16* __restrict__ BL,
              float* __restrict__ Cf,
              __nv_bfloat16* __restrict__ CH, __nv_bfloat16* __restrict__ CL,
              const float* __restrict__ G,
              const int* __restrict__ rows, const int* __restrict__ cnt,
              int Mfull, int N, int Kd,
              long long sA, long long sB, long long sC)
{
    extern __shared__ char dsm[];
    const int z = blockIdx.z;
    int Mz = Mfull;
    if (cnt) { int c = cnt[z]; Mz = c < Mfull ? c : Mfull; }
    const int yblk = blockIdx.y * 128;
    if (yblk >= Mz) return;
    const int xblk = blockIdx.x * 128;

    const uint32_t sm = smem_u32(dsm);
    const int tid = threadIdx.x;
    const int wid = tid >> 5;
    const int lid = tid & 31;

    // ---- cp.async plan: 1 granule each of AH/AL/BH/BL per thread per stage --
    // A: tid -> row = tid>>2 (0..127), q = tid&3 (16B within 64B row-chunk)
    // B: tid -> k  = tid>>4 (0..31),  q2 = tid&15 (16B within 256B n-row)
    const char *aSrcH, *aSrcL, *bSrcH, *bSrcL;
    uint32_t aDst, bDst;
    {
        int row = tid >> 2, q = tid & 3;
        int mg = yblk + row;
        long long r;
        if (GATHER) r = (mg < Mz) ? (long long)rows[z * CAP_ + mg] : 0;
        else        r = mg;
        const __nv_bfloat16* baseH = GATHER ? AH : (AH + (size_t)z * sA);
        const __nv_bfloat16* baseL = GATHER ? AL : (AL + (size_t)z * sA);
        aSrcH = (const char*)(baseH + r * (long long)Kd) + q * 16;
        aSrcL = (const char*)(baseL + r * (long long)Kd) + q * 16;
        aDst  = (uint32_t)row * A_STR + q * 16;

        int k = tid >> 4, q2 = tid & 15;
        bSrcH = (const char*)(BH + (size_t)z * sB + (size_t)k * N + xblk) + q2 * 16;
        bSrcL = (const char*)(BL + (size_t)z * sB + (size_t)k * N + xblk) + q2 * 16;
        bDst  = (uint32_t)k * B_STR + q2 * 16;
    }

    const int nch = Kd / 32;
    auto issueStage = [&](int ch) {
        if (ch >= nch) return;
        const uint32_t base = sm + (uint32_t)(ch % NSTAGE) * STAGE_SZ;
        const size_t aoff = (size_t)ch * 64;            // 32 bf16 = 64 bytes
        const size_t boff = (size_t)ch * 32 * N * 2;    // 32 k-rows
        cpa16(base + O_AH + aDst, aSrcH + aoff);
        cpa16(base + O_AL + aDst, aSrcL + aoff);
        cpa16(base + O_BH + bDst, bSrcH + boff);
        cpa16(base + O_BL + bDst, bSrcL + boff);
    };

    // ---- warp compute geometry: warp (wm, wn) owns rows wm*32.., cols wn*32 --
    const int wm = wid & 3;
    const int wn = wid >> 2;
    const int l15 = lid & 15, lh = lid >> 4;
    const uint32_t aLaneH = O_AH + (uint32_t)(wm * 32 + l15) * A_STR + lh * 16;
    const uint32_t aLaneL = O_AL + (uint32_t)(wm * 32 + l15) * A_STR + lh * 16;
    const uint32_t bLaneH = O_BH + (uint32_t)l15 * B_STR + (uint32_t)(wn * 32 + lh * 8) * 2;
    const uint32_t bLaneL = O_BL + (uint32_t)l15 * B_STR + (uint32_t)(wn * 32 + lh * 8) * 2;

    float acc[2][4][4];
#pragma unroll
    for (int mt = 0; mt < 2; mt++)
#pragma unroll
        for (int nt = 0; nt < 4; nt++)
#pragma unroll
            for (int q = 0; q < 4; q++) acc[mt][nt][q] = 0.f;

    // ---- prologue: stages 0 and 1 in flight ----
    issueStage(0); CP_COMMIT();
    issueStage(1); CP_COMMIT();

    for (int ch = 0; ch < nch; ch++) {
        CP_WAIT1();
        __syncthreads();        // single barrier per chunk (see hazard note)

        issueStage(ch + 2);
        CP_COMMIT();

        const uint32_t curB = (uint32_t)(ch % NSTAGE) * STAGE_SZ;
        const uint32_t aH = sm + curB + aLaneH;
        const uint32_t aL = sm + curB + aLaneL;
        const uint32_t bH = sm + curB + bLaneH;
        const uint32_t bL = sm + curB + bLaneL;
#pragma unroll
        for (int kk = 0; kk < 2; kk++) {
            uint32_t ah[2][4], al[2][4], bh[2][4], bl[2][4];
#pragma unroll
            for (int mt = 0; mt < 2; mt++) {
                ldsm4(ah[mt], aH + mt * 16 * A_STR + kk * 32);
                ldsm4(al[mt], aL + mt * 16 * A_STR + kk * 32);
            }
#pragma unroll
            for (int nt = 0; nt < 2; nt++) {
                ldsm4t(bh[nt], bH + kk * 16 * B_STR + nt * 32);
                ldsm4t(bl[nt], bL + kk * 16 * B_STR + nt * 32);
            }
#pragma unroll
            for (int mt = 0; mt < 2; mt++)
#pragma unroll
                for (int nt = 0; nt < 2; nt++) {
                    mma16816(acc[mt][2 * nt],     ah[mt], &bh[nt][0]);
                    mma16816(acc[mt][2 * nt + 1], ah[mt], &bh[nt][2]);
                    mma16816(acc[mt][2 * nt],     ah[mt], &bl[nt][0]);
                    mma16816(acc[mt][2 * nt + 1], ah[mt], &bl[nt][2]);
                    mma16816(acc[mt][2 * nt],     al[mt], &bh[nt][0]);
                    mma16816(acc[mt][2 * nt + 1], al[mt], &bh[nt][2]);
                }
        }
        // NOTE: no bottom barrier — the top barrier of iteration ch+1 already
        // separates this MMA phase from issueStage(ch+3), which is the only
        // writer that could touch stage (ch % NSTAGE) next.
    }

    // ---- epilogue ----
    const int group = lid >> 2, tig = lid & 3;
#pragma unroll
    for (int mt = 0; mt < 2; mt++) {
        int r0 = yblk + wm * 32 + mt * 16 + group;
#pragma unroll
        for (int half = 0; half < 2; half++) {
            int r = r0 + half * 8;
            if (r < Mz) {
                size_t rowoff = (size_t)r * N;
#pragma unroll
                for (int nt = 0; nt < 4; nt++) {
                    int col = xblk + wn * 32 + nt * 8 + 2 * tig;
                    float d0 = acc[mt][nt][2 * half];
                    float d1 = acc[mt][nt][2 * half + 1];
                    size_t off = (size_t)z * sC + rowoff + col;
                    if (EPI == 0) {
                        *(float2*)&Cf[off] = make_float2(d0, d1);
                    } else {
                        float2 g = *(const float2*)&G[off];
                        d0 *= g.x / (1.f + __expf(-g.x));
                        d1 *= g.y / (1.f + __expf(-g.y));
                        *(uint32_t*)&CH[off] = pack_hi(d0, d1);
                        *(uint32_t*)&CL[off] = pack_lo(d0, d1);
                    }
                }
            }
        }
    }
}

// ---------------- combine: out[t] += sum_k w * eout[e_k, pos_k] --------------
__global__ void combine_kernel(float* __restrict__ out)
{
    int t   = blockIdx.x;
    int tid = threadIdx.x;

    const float* rp[K_]; float w[K_]; bool v[K_];
#pragma unroll
    for (int k = 0; k < K_; k++) {
        int p = g_pos[t * K_ + k];
        int e = g_ti[t * K_ + k];
        w[k]  = g_tw[t * K_ + k];
        v[k]  = (p >= 0);
        int pc = p < 0 ? 0 : p;
        rp[k] = g_Eout + ((size_t)e * CAP_ + pc) * H_;
    }
#pragma unroll
    for (int j = 0; j < 2; j++) {
        int c4 = tid + j * 256;
        size_t off = (size_t)t * H_ + c4 * 4;
        float4 a = *(float4*)&out[off];
#pragma unroll
        for (int k = 0; k < K_; k++) {
            if (v[k]) {
                float4 xv = *(const float4*)&rp[k][c4 * 4];
                a.x += w[k] * xv.x; a.y += w[k] * xv.y;
                a.z += w[k] * xv.z; a.w += w[k] * xv.w;
            }
        }
        *(float4*)&out[off] = a;
    }
}

// ---------------- launch ------------------------------------------------------
extern "C" void kernel_launch(void* const* d_in, const int* in_sizes, int n_in,
                              void* d_out, int out_size)
{
    const float* x       = (const float*)d_in[0];
    const float* gate_w  = (const float*)d_in[1];
    const float* w_gate  = (const float*)d_in[2];
    const float* w_up    = (const float*)d_in[3];
    const float* w_down  = (const float*)d_in[4];
    const float* sw_gate = (const float*)d_in[5];
    const float* sw_up   = (const float*)d_in[6];
    const float* sw_down = (const float*)d_in[7];
    float* out = (float*)d_out;

    float *Gr, *Eo, *Gs;
    int *buf, *cnt;
    __nv_bfloat16 *xH, *xL, *wgH, *wgL, *wuH, *wuL, *wdH, *wdL;
    __nv_bfloat16 *sgH, *sgL, *suH, *suL, *sdH, *sdL, *MrH, *MrL, *MsH, *MsL;
    cudaGetSymbolAddress((void**)&Gr,  g_Gr);
    cudaGetSymbolAddress((void**)&Eo,  g_Eout);
    cudaGetSymbolAddress((void**)&Gs,  g_Gs);
    cudaGetSymbolAddress((void**)&buf, g_buf);
    cudaGetSymbolAddress((void**)&cnt, g_cnt);
    cudaGetSymbolAddress((void**)&xH,  g_xH);  cudaGetSymbolAddress((void**)&xL,  g_xL);
    cudaGetSymbolAddress((void**)&wgH, g_wgH); cudaGetSymbolAddress((void**)&wgL, g_wgL);
    cudaGetSymbolAddress((void**)&wuH, g_wuH); cudaGetSymbolAddress((void**)&wuL, g_wuL);
    cudaGetSymbolAddress((void**)&wdH, g_wdH); cudaGetSymbolAddress((void**)&wdL, g_wdL);
    cudaGetSymbolAddress((void**)&sgH, g_sgH); cudaGetSymbolAddress((void**)&sgL, g_sgL);
    cudaGetSymbolAddress((void**)&suH, g_suH); cudaGetSymbolAddress((void**)&suL, g_suL);
    cudaGetSymbolAddress((void**)&sdH, g_sdH); cudaGetSymbolAddress((void**)&sdL, g_sdL);
    cudaGetSymbolAddress((void**)&MrH, g_MrH); cudaGetSymbolAddress((void**)&MrL, g_MrL);
    cudaGetSymbolAddress((void**)&MsH, g_MsH); cudaGetSymbolAddress((void**)&MsL, g_MsL);

    cudaFuncSetAttribute(mma_gemm<true, 0>,  cudaFuncAttributeMaxDynamicSharedMemorySize, SM_DYN);
    cudaFuncSetAttribute(mma_gemm<true, 1>,  cudaFuncAttributeMaxDynamicSharedMemorySize, SM_DYN);
    cudaFuncSetAttribute(mma_gemm<false, 0>, cudaFuncAttributeMaxDynamicSharedMemorySize, SM_DYN);
    cudaFuncSetAttribute(mma_gemm<false, 1>, cudaFuncAttributeMaxDynamicSharedMemorySize, SM_DYN);

    // 0) preconvert fp32 -> bf16 hi/lo pairs
    auto cvt = [&](const float* s, __nv_bfloat16* h, __nv_bfloat16* l, long long n) {
        int n4 = (int)(n / 4);
        cvt_pair_kernel<<<(n4 + 255) / 256, 256>>>(s, h, l, n4);
    };
    cvt(x,       xH,  xL,  (long long)T_ * H_);
    cvt(w_gate,  wgH, wgL, (long long)E_ * H_ * I_);
    cvt(w_up,    wuH, wuL, (long long)E_ * H_ * I_);
    cvt(w_down,  wdH, wdL, (long long)E_ * I_ * H_);
    cvt(sw_gate, sgH, sgL, (long long)H_ * IS_);
    cvt(sw_up,   suH, suL, (long long)H_ * IS_);
    cvt(sw_down, sdH, sdL, (long long)IS_ * H_);

    // 1) routing
    gate_topk_kernel<<<T_, 256>>>(x, gate_w);
    dispatch_kernel<<<E_, 256>>>();

    // 2) routed experts
    dim3 g1(I_ / 128, CAP_ / 128, E_);
    mma_gemm<true, 0><<<g1, 512, SM_DYN>>>(xH, xL, wgH, wgL, Gr, nullptr, nullptr, nullptr,
        buf, cnt, CAP_, I_, H_, 0, (long long)H_ * I_, (long long)CAP_ * I_);
    mma_gemm<true, 1><<<g1, 512, SM_DYN>>>(xH, xL, wuH, wuL, nullptr, MrH, MrL, Gr,
        buf, cnt, CAP_, I_, H_, 0, (long long)H_ * I_, (long long)CAP_ * I_);
    dim3 g2(H_ / 128, CAP_ / 128, E_);
    mma_gemm<false, 0><<<g2, 512, SM_DYN>>>(MrH, MrL, wdH, wdL, Eo, nullptr, nullptr, nullptr,
        nullptr, cnt, CAP_, H_, I_, (long long)CAP_ * I_, (long long)I_ * H_, (long long)CAP_ * H_);

    // 3) shared expert
    dim3 g3(IS_ / 128, T_ / 128, 1);
    mma_gemm<false, 0><<<g3, 512, SM_DYN>>>(xH, xL, sgH, sgL, Gs, nullptr, nullptr, nullptr,
        nullptr, nullptr, T_, IS_, H_, 0, 0, 0);
    mma_gemm<false, 1><<<g3, 512, SM_DYN>>>(xH, xL, suH, suL, nullptr, MsH, MsL, Gs,
        nullptr, nullptr, T_, IS_, H_, 0, 0, 0);
    dim3 g4(H_ / 128, T_ / 128, 1);
    mma_gemm<false, 0><<<g4, 512, SM_DYN>>>(MsH, MsL, sdH, sdL, out, nullptr, nullptr, nullptr,
        nullptr, nullptr, T_, H_, IS_, 0, 0, 0);

    // 4) combine routed contributions (deterministic gather, no atomics)
    combine_kernel<<<T_, 256>>>(out);
}